// round 3
// baseline (speedup 1.0000x reference)
#include <cuda_runtime.h>

// ---------------------------------------------------------------------------
// GATv2 layer — algebraically collapsed.
// H[n] = has_incoming_edge(n) ? (V[n] @ Wv.T + Wv_b) : 0
// (softmax weights over each dest segment sum to 1; Vv depends only on dest)
//
// GEMM inner loop uses packed fma.rn.f32x2 (FFMA2): each accumulator is a
// 64-bit register holding partial sums over even/odd k; halves the FMA-pipe
// issue count vs scalar FFMA (rt_SMSP=2 either way, 2x work per issue).
// ---------------------------------------------------------------------------

#define D_DIM 128
#define BM 64          // node rows per block
#define BK 32          // k-tile
#define TM 8           // rows per thread
#define TN 4           // cols per thread (cols cg, cg+32, cg+64, cg+96)
#define THREADS 256

#define MAX_NODES 50048

__device__ unsigned char g_has_edge[MAX_NODES];
__device__ int g_is64;

// ---------------------------------------------------------------------------
// Zero mask + detect edge_index dtype in one kernel.
// int64 detection: odd 32-bit words of the first 64 values are hi-words,
// all zero for node ids < 2^31. For int32 they are live indices.
// ---------------------------------------------------------------------------
__global__ void zero_detect_kernel(const unsigned int* __restrict__ ei, int n) {
    int i = blockIdx.x * blockDim.x + threadIdx.x;
    if (i < n) g_has_edge[i] = 0;
    if (blockIdx.x == 0 && threadIdx.x < 32) {
        unsigned int v = ei[2 * threadIdx.x + 1];
        unsigned int any = __ballot_sync(0xFFFFFFFFu, v != 0u);
        if (threadIdx.x == 0) g_is64 = (any == 0u) ? 1 : 0;
    }
}

// ---------------------------------------------------------------------------
// Mark nodes that appear as a destination (row 1 of edge_index).
// ---------------------------------------------------------------------------
__global__ void set_mask_kernel(const void* __restrict__ ei, int E) {
    int e = blockIdx.x * blockDim.x + threadIdx.x;
    if (e >= E) return;
    int d;
    if (g_is64) {
        d = (int)((const long long*)ei)[E + e];
    } else {
        d = ((const int*)ei)[E + e];
    }
    g_has_edge[d] = 1;
}

// ---------------------------------------------------------------------------
// Packed dual-FMA: {acc.lo += a.lo*b.lo, acc.hi += a.hi*b.hi}
// ---------------------------------------------------------------------------
__device__ __forceinline__ void ffma2(unsigned long long& acc,
                                      unsigned long long a,
                                      unsigned long long b) {
    asm("fma.rn.f32x2 %0, %1, %2, %0;" : "+l"(acc) : "l"(a), "l"(b));
}

__device__ __forceinline__ float reduce2(unsigned long long a) {
    return __uint_as_float((unsigned int)a) +
           __uint_as_float((unsigned int)(a >> 32));
}

// ---------------------------------------------------------------------------
// out[n][o] = mask[n] * (sum_k V[n][k] * W[o][k] + b[o])
//
// Block: 64 rows x 128 cols, 256 threads. Thread (cg=tid%32, rg=tid/32)
// computes rows 8*rg..8*rg+7, cols {cg, cg+32, cg+64, cg+96}.
// W tile XOR-swizzled in shared; V tile reads are warp-broadcast.
// Accumulators are f32x2 partial sums over the k-pair lanes.
// ---------------------------------------------------------------------------
__global__ __launch_bounds__(THREADS) void vproj_kernel(
    const float* __restrict__ V,
    const float* __restrict__ W,
    const float* __restrict__ b,
    float* __restrict__ out,
    int N)
{
    __shared__ float4 Vs[BM][BK / 4];       // [64][8]  8 KB
    __shared__ float4 Ws[D_DIM][BK / 4];    // [128][8] 16 KB

    const int tid = threadIdx.x;
    const int cg  = tid & 31;               // column group
    const int rg  = tid >> 5;               // row group (0..7)
    const int row0 = blockIdx.x * BM;

    const int lf = tid & 7;                 // float4 index within a row (load)
    const int lr = tid >> 3;                // row index (load), 0..31

    // bias loads early: independent of the mainloop, hide under k-loop
    float bias[TN];
    #pragma unroll
    for (int c = 0; c < TN; c++)
        bias[c] = __ldg(&b[cg + 32 * c]);

    unsigned long long acc[TM][TN];
    #pragma unroll
    for (int r = 0; r < TM; r++)
        #pragma unroll
        for (int c = 0; c < TN; c++)
            acc[r][c] = 0ULL;

    for (int kt = 0; kt < D_DIM; kt += BK) {
        // ---- load V tile (guarded) ----
        #pragma unroll
        for (int rr = lr; rr < BM; rr += 32) {
            int gr = row0 + rr;
            float4 val = make_float4(0.f, 0.f, 0.f, 0.f);
            if (gr < N)
                val = *(const float4*)&V[(long long)gr * D_DIM + kt + 4 * lf];
            Vs[rr][lf] = val;
        }
        // ---- load W tile, XOR-swizzled ----
        #pragma unroll
        for (int cc = lr; cc < D_DIM; cc += 32) {
            float4 wv = *(const float4*)&W[(long long)cc * D_DIM + kt + 4 * lf];
            Ws[cc][lf ^ (cc & 7)] = wv;
        }
        __syncthreads();

        // ---- compute (FFMA2 over k-pairs) ----
        #pragma unroll
        for (int kk4 = 0; kk4 < BK / 4; kk4++) {
            ulonglong2 w2[TN];
            #pragma unroll
            for (int c = 0; c < TN; c++) {
                int col = cg + 32 * c;                  // (col & 7) == (cg & 7)
                w2[c] = *(const ulonglong2*)&Ws[col][kk4 ^ (cg & 7)];
            }
            #pragma unroll
            for (int r = 0; r < TM; r++) {
                ulonglong2 v2 =
                    *(const ulonglong2*)&Vs[TM * rg + r][kk4];  // broadcast
                #pragma unroll
                for (int c = 0; c < TN; c++) {
                    ffma2(acc[r][c], v2.x, w2[c].x);
                    ffma2(acc[r][c], v2.y, w2[c].y);
                }
            }
        }
        __syncthreads();
    }

    // ---- epilogue: reduce pairs, bias, mask, store ----
    #pragma unroll
    for (int r = 0; r < TM; r++) {
        int gr = row0 + TM * rg + r;
        if (gr >= N) continue;
        float fl = (float)g_has_edge[gr];
        #pragma unroll
        for (int c = 0; c < TN; c++) {
            out[(long long)gr * D_DIM + cg + 32 * c] =
                fl * (reduce2(acc[r][c]) + bias[c]);
        }
    }
}

// ---------------------------------------------------------------------------
// Inputs (metadata order):
//  0: V [N,128] f32   2: edge_index [2,E] i64/i32
//  7: Wv_w [128,128]  8: Wv_b [128]       (others unused)
// ---------------------------------------------------------------------------
extern "C" void kernel_launch(void* const* d_in, const int* in_sizes, int n_in,
                              void* d_out, int out_size) {
    const float* V    = (const float*)d_in[0];
    const void*  ei   = d_in[2];
    const float* Wv_w = (const float*)d_in[7];
    const float* Wv_b = (const float*)d_in[8];
    float* out = (float*)d_out;

    int N = in_sizes[0] / D_DIM;
    int E = in_sizes[2] / 2;
    if (N > MAX_NODES) N = MAX_NODES;  // safety; problem is N=50000

    zero_detect_kernel<<<(N + 255) / 256, 256>>>((const unsigned int*)ei, N);
    set_mask_kernel<<<(E + 255) / 256, 256>>>(ei, E);
    vproj_kernel<<<(N + BM - 1) / BM, THREADS>>>(V, Wv_w, Wv_b, out, N);
}